// round 7
// baseline (speedup 1.0000x reference)
#include <cuda_runtime.h>

// Toy force field: f = -grad_p( sum(MLP(p)) ), MLP = 2 -> 8 -> 4 -> 2 with ReLU.
//
// Key fact: f depends on pos ONLY through the 12 ReLU mask bits:
//   m1 (8 bits, layer-1 signs) and m2 (4 bits, layer-2 signs).
//   f = W1^T ( m1 .* ( -W2^T (m2 .* v) ) ),   v = colsum(W3).
// So precompute the FULL answer: F[m2<<8 | m1] = (fx, fy), 4096 x float2 = 32KB shared.
// Per sample: forward pass for the 12 sign bits, then ONE LDS.64. No backward math.

#define NTHREADS 256
#define NBLOCKS  296     // 148 SMs x 2 CTAs -> exactly one wave
#define ILP      4

__global__ __launch_bounds__(NTHREADS, 2) void toy_force_kernel(
    const float4* __restrict__ pos4,
    const float*  __restrict__ W1g,
    const float*  __restrict__ b1g,
    const float*  __restrict__ W2g,
    const float*  __restrict__ b2g,
    const float*  __restrict__ W3g,
    float4*       __restrict__ out4,
    int npairs)
{
    __shared__ float sW1[16];
    __shared__ float sb1[8];
    __shared__ float sW2[32];
    __shared__ float sb2[4];
    __shared__ float sv[4];
    __shared__ __align__(8) float2 F[4096];   // F[m2*256 + m1]

    const int t = threadIdx.x;

    // Stage raw weights into shared.
    if (t < 16)               sW1[t]      = W1g[t];
    else if (t < 24)          sb1[t - 16] = b1g[t - 16];
    else if (t < 56)          sW2[t - 24] = W2g[t - 24];
    else if (t < 60)          sb2[t - 56] = b2g[t - 56];
    else if (t < 64)          sv[t - 60]  = W3g[t - 60] + W3g[4 + (t - 60)];
    __syncthreads();

    // ---- Build the full force LUT: 16 entries per thread ----
    // Thread t owns m2 = t & 15 and the high nibble of m1 = t >> 4.
    {
        const int m2  = t & 15;
        const int mhi = t >> 4;   // m1 bits 4..7

        // g[j] = -(sum_k m2_k * v[k] * W2[k][j])
        float g[8];
#pragma unroll
        for (int j = 0; j < 8; j++) {
            float a = 0.f;
#pragma unroll
            for (int k = 0; k < 4; k++)
                if (m2 & (1 << k)) a += sv[k] * sW2[k * 8 + j];
            g[j] = -a;
        }

        // Partial force from m1's high nibble (neurons 4..7).
        float phx = 0.f, phy = 0.f;
#pragma unroll
        for (int jj = 0; jj < 4; jj++) {
            if (mhi & (1 << jj)) {
                phx += g[4 + jj] * sW1[2 * (4 + jj)];
                phy += g[4 + jj] * sW1[2 * (4 + jj) + 1];
            }
        }

        // Sweep m1's low nibble.
#pragma unroll
        for (int mlo = 0; mlo < 16; mlo++) {
            float fx = phx, fy = phy;
#pragma unroll
            for (int jj = 0; jj < 4; jj++) {
                if (mlo & (1 << jj)) {
                    fx += g[jj] * sW1[2 * jj];
                    fy += g[jj] * sW1[2 * jj + 1];
                }
            }
            F[(m2 << 8) | (mhi << 4) | mlo] = make_float2(fx, fy);
        }
    }
    __syncthreads();

    // ---- Per-thread register copies of forward weights ----
    float w10[8], w11[8], b1r[8], W2r[4][8], b2r[4];
#pragma unroll
    for (int j = 0; j < 8; j++) {
        w10[j] = sW1[2 * j];
        w11[j] = sW1[2 * j + 1];
        b1r[j] = sb1[j];
    }
#pragma unroll
    for (int k = 0; k < 4; k++) {
        b2r[k] = sb2[k];
#pragma unroll
        for (int j = 0; j < 8; j++) W2r[k][j] = sW2[k * 8 + j];
    }

    const int TOT = gridDim.x * blockDim.x;
    const int i0  = blockIdx.x * blockDim.x + t;

    for (int base = i0; base < npairs; base += ILP * TOT) {
        // Batched independent loads (MLP = 4).
        float4 p[ILP];
        bool ok[ILP];
#pragma unroll
        for (int u = 0; u < ILP; u++) {
            const int i = base + u * TOT;
            ok[u] = (i < npairs);
            if (ok[u]) p[u] = pos4[i];
        }

#pragma unroll
        for (int u = 0; u < ILP; u++) {
            if (!ok[u]) continue;
            float fo[4];
#pragma unroll
            for (int s = 0; s < 2; s++) {
                const float x = s ? p[u].z : p[u].x;
                const float y = s ? p[u].w : p[u].y;

                // Layer 1 forward + m1 bits
                float h1[8];
                int m1 = 0;
#pragma unroll
                for (int j = 0; j < 8; j++) {
                    const float h1p = fmaf(x, w10[j], fmaf(y, w11[j], b1r[j]));
                    m1 |= (h1p > 0.f) ? (1 << j) : 0;
                    h1[j] = fmaxf(h1p, 0.f);
                }

                // Layer 2 forward -> m2 bits (pre-shifted by 8)
                int m2 = 0;
#pragma unroll
                for (int k = 0; k < 4; k++) {
                    float a = b2r[k];
#pragma unroll
                    for (int j = 0; j < 8; j++) a = fmaf(h1[j], W2r[k][j], a);
                    m2 |= (a > 0.f) ? (256 << k) : 0;
                }

                // The answer is a single LDS.64.
                const float2 f = F[m2 | m1];
                fo[2 * s]     = f.x;
                fo[2 * s + 1] = f.y;
            }
            out4[base + u * TOT] = make_float4(fo[0], fo[1], fo[2], fo[3]);
        }
    }
}

extern "C" void kernel_launch(void* const* d_in, const int* in_sizes, int n_in,
                              void* d_out, int out_size) {
    const float4* pos4 = (const float4*)d_in[0];
    const float*  W1   = (const float*)d_in[1];
    const float*  b1   = (const float*)d_in[2];
    const float*  W2   = (const float*)d_in[3];
    const float*  b2   = (const float*)d_in[4];
    const float*  W3   = (const float*)d_in[5];
    float4*       out4 = (float4*)d_out;

    const int npairs = in_sizes[0] / 4;   // floats -> float4 count (2 samples each)

    toy_force_kernel<<<NBLOCKS, NTHREADS>>>(pos4, W1, b1, W2, b2, W3, out4, npairs);
}